// round 6
// baseline (speedup 1.0000x reference)
#include <cuda_runtime.h>
#include <cuda_bf16.h>
#include <cstdint>

#define NPTS 16384
#define MP   4096
#define KNB  16

// ---------------- helpers ----------------
__device__ __forceinline__ uint32_t s2u(const void* p) {
    uint32_t a;
    asm("{ .reg .u64 t; cvta.to.shared.u64 t, %1; cvt.u32.u64 %0, t; }" : "=r"(a) : "l"(p));
    return a;
}
#define CP16(dst, src) asm volatile("cp.async.cg.shared.global [%0], [%1], 16;" :: "r"(dst), "l"(src))
#define CP_COMMIT()    asm volatile("cp.async.commit_group;" ::: "memory")
#define CP_WAIT0()     asm volatile("cp.async.wait_group 0;" ::: "memory")
#define CP_WAIT1()     asm volatile("cp.async.wait_group 1;" ::: "memory")

// [128][128] bf16 tile, 256B rows, 16B chunks XOR-swizzled by row
__device__ __forceinline__ uint32_t tile_off(int r, int c16) {
    return (uint32_t)(r * 256 + ((c16 ^ (r & 7)) << 4));
}
__device__ __forceinline__ void fill_async(uint32_t dst, const __nv_bfloat16* __restrict__ src, int tid) {
#pragma unroll
    for (int it = 0; it < 8; it++) {
        int idx = tid + it * 256;
        int r = idx >> 4, c16 = idx & 15;
        CP16(dst + tile_off(r, c16), src + r * 128 + c16 * 8);
    }
}
__device__ __forceinline__ void ldmA(uint32_t* a, uint32_t base, int mrow, int kcol, int lane) {
    uint32_t addr = base + tile_off(mrow + (lane & 15), (kcol >> 3) + (lane >> 4));
    asm volatile("ldmatrix.sync.aligned.m8n8.x4.shared.b16 {%0,%1,%2,%3}, [%4];"
        : "=r"(a[0]), "=r"(a[1]), "=r"(a[2]), "=r"(a[3]) : "r"(addr));
}
__device__ __forceinline__ void ldmB(uint32_t* b, uint32_t base, int ncol, int kcol, int lane) {
    uint32_t addr = base + tile_off(ncol + (lane & 7), (kcol >> 3) + ((lane >> 3) & 1));
    asm volatile("ldmatrix.sync.aligned.m8n8.x2.shared.b16 {%0,%1}, [%2];"
        : "=r"(b[0]), "=r"(b[1]) : "r"(addr));
}
__device__ __forceinline__ void mma16816(float* d, const uint32_t* a, const uint32_t* b) {
    asm volatile("mma.sync.aligned.m16n8k16.row.col.f32.bf16.bf16.f32 "
        "{%0,%1,%2,%3}, {%4,%5,%6,%7}, {%8,%9}, {%0,%1,%2,%3};"
        : "+f"(d[0]), "+f"(d[1]), "+f"(d[2]), "+f"(d[3])
        : "r"(a[0]), "r"(a[1]), "r"(a[2]), "r"(a[3]), "r"(b[0]), "r"(b[1]));
}
__device__ __forceinline__ float leaky_f(float v) { return v < 0.f ? 0.2f * v : v; }

// split-bf16 3-product 128x128x128 tile: warp (wm,wn) owns 64x32
__device__ __forceinline__ void mma_core(uint32_t sA, uint32_t sB, int wm, int wn, int lane,
                                         float acc[4][4][4]) {
#pragma unroll 1
    for (int ks = 0; ks < 8; ks++) {
        const int kc = ks * 16;
        uint32_t ah[4][4], al[4][4], bh[4][2], bl[4][2];
#pragma unroll
        for (int mi = 0; mi < 4; mi++) {
            ldmA(ah[mi], sA, wm * 64 + mi * 16, kc, lane);
            ldmA(al[mi], sA + 32768, wm * 64 + mi * 16, kc, lane);
        }
#pragma unroll
        for (int ni = 0; ni < 4; ni++) {
            ldmB(bh[ni], sB, wn * 32 + ni * 8, kc, lane);
            ldmB(bl[ni], sB + 32768, wn * 32 + ni * 8, kc, lane);
        }
#pragma unroll
        for (int mi = 0; mi < 4; mi++)
#pragma unroll
            for (int ni = 0; ni < 4; ni++) {
                mma16816(acc[mi][ni], ah[mi], bh[ni]);
                mma16816(acc[mi][ni], ah[mi], bl[ni]);
                mma16816(acc[mi][ni], al[mi], bh[ni]);
            }
    }
}
#define ACC_ZERO(acc) do { \
    _Pragma("unroll") for (int mi = 0; mi < 4; mi++) \
    _Pragma("unroll") for (int ni = 0; ni < 4; ni++) \
    _Pragma("unroll") for (int j = 0; j < 4; j++) acc[mi][ni][j] = 0.f; } while (0)

// ---------------- scratch ----------------
__device__ __nv_bfloat16 g_sh[81920 * 128], g_sl[81920 * 128];
__device__ __nv_bfloat16 g_w1h[128 * 128],  g_w1l[128 * 128];
__device__ __nv_bfloat16 g_w2h[1024 * 128], g_w2l[1024 * 128];
__device__ __nv_bfloat16 g_wlh[512 * 128],  g_wll[512 * 128];
__device__ __nv_bfloat16 g_wrh[512 * 128],  g_wrl[512 * 128];
__device__ float g_xn[65536];
__device__ float g_XLR[5 * 16384 * 512];
__device__ float g_gf[5 * 4 * 1024];
__device__ float g_attn[16];
__device__ int   g_nbr[4 * 16384 * 16];
__device__ float g_res[4 * 16384 * 128];

// ---------------- preludes ----------------
__global__ void zero_gf_kernel() {
    int i = blockIdx.x * 256 + threadIdx.x;
    if (i < 5 * 4 * 1024) g_gf[i] = 0.f;
}
__global__ void split_seq_kernel(const float* __restrict__ seq) {
    size_t i = (size_t)blockIdx.x * 256 + threadIdx.x;
    float4 v = ((const float4*)seq)[i];
    float x[4] = {v.x, v.y, v.z, v.w};
    unsigned short h[4], l[4];
#pragma unroll
    for (int j = 0; j < 4; j++) {
        __nv_bfloat16 hb = __float2bfloat16(x[j]);
        h[j] = __bfloat16_as_ushort(hb);
        l[j] = __bfloat16_as_ushort(__float2bfloat16(x[j] - __bfloat162float(hb)));
    }
    uint2 H, L;
    H.x = ((uint32_t)h[1] << 16) | h[0]; H.y = ((uint32_t)h[3] << 16) | h[2];
    L.x = ((uint32_t)l[1] << 16) | l[0]; L.y = ((uint32_t)l[3] << 16) | l[2];
    ((uint2*)g_sh)[i] = H; ((uint2*)g_sl)[i] = L;
}
__global__ void norm_kernel(const float* __restrict__ seq) {
    int r = blockIdx.x * 128 + threadIdx.x;
    const float4* p = (const float4*)(seq + (size_t)r * 128);
    float s = 0.f;
#pragma unroll 8
    for (int i = 0; i < 32; i++) { float4 v = p[i]; s += v.x*v.x + v.y*v.y + v.z*v.z + v.w*v.w; }
    g_xn[r] = s;
}
__global__ void tsplit_kernel(const float* __restrict__ src, __nv_bfloat16* __restrict__ dh,
                              __nv_bfloat16* __restrict__ dl, int N) {
    __shared__ float t[32][33];
    int n0 = blockIdx.x * 32, k0 = blockIdx.y * 32;
    int tx = threadIdx.x, ty = threadIdx.y;
#pragma unroll
    for (int j = 0; j < 4; j++) t[ty + 8 * j][tx] = src[(size_t)(k0 + ty + 8 * j) * N + n0 + tx];
    __syncthreads();
#pragma unroll
    for (int j = 0; j < 4; j++) {
        int n = n0 + ty + 8 * j, k = k0 + tx;
        float v = t[tx][ty + 8 * j];
        __nv_bfloat16 hb = __float2bfloat16(v);
        dh[(size_t)n * 128 + k] = hb;
        dl[(size_t)n * 128 + k] = __float2bfloat16(v - __bfloat162float(hb));
    }
}

// ---------------- fused H1 + gf: A resident, W2 streamed double-buffered ----------------
#define GFSM 196608
__global__ __launch_bounds__(256, 1) void gf_kernel(const float* __restrict__ b1,
                                                    const float* __restrict__ b2) {
    extern __shared__ char sm[];
    const uint32_t sA = s2u(sm), sB0 = sA + 65536, sB1 = sA + 131072;
    const int tid = threadIdx.x, lane = tid & 31, wid = tid >> 5;
    const int wm = wid & 1, wn = wid >> 1;
    const size_t row0 = (size_t)blockIdx.x * 128;

    fill_async(sA, g_sh + row0 * 128, tid);
    fill_async(sA + 32768, g_sl + row0 * 128, tid);
    fill_async(sB0, g_w1h, tid);
    fill_async(sB0 + 32768, g_w1l, tid);
    CP_COMMIT(); CP_WAIT0(); __syncthreads();

    float acc[4][4][4];
    ACC_ZERO(acc);
    mma_core(sA, sB0, wm, wn, lane, acc);
    __syncthreads();                               // A/B0 reads done

    // prefetch W2[0]->B0, W2[1]->B1 (overlaps H1 write below)
    fill_async(sB0, g_w2h, tid); fill_async(sB0 + 32768, g_w2l, tid); CP_COMMIT();
    fill_async(sB1, g_w2h + 16384, tid); fill_async(sB1 + 32768, g_w2l + 16384, tid); CP_COMMIT();

    // H1 = leaky(acc + b1) written split-bf16 into A (tile format), from registers
#pragma unroll
    for (int mi = 0; mi < 4; mi++)
#pragma unroll
        for (int ni = 0; ni < 4; ni++) {
            int r = wm * 64 + mi * 16 + (lane >> 2);
            int c = wn * 32 + ni * 8 + (lane & 3) * 2;
            float2 bv = *(const float2*)(b1 + c);
#pragma unroll
            for (int half = 0; half < 2; half++) {
                int rr = r + half * 8;
                float v0 = leaky_f(acc[mi][ni][half * 2]     + bv.x);
                float v1 = leaky_f(acc[mi][ni][half * 2 + 1] + bv.y);
                __nv_bfloat16 h0 = __float2bfloat16(v0), h1 = __float2bfloat16(v1);
                __nv_bfloat16 l0 = __float2bfloat16(v0 - __bfloat162float(h0));
                __nv_bfloat16 l1 = __float2bfloat16(v1 - __bfloat162float(h1));
                uint32_t off = tile_off(rr, c >> 3) + (c & 7) * 2;
                *(uint32_t*)(sm + off) =
                    ((uint32_t)__bfloat16_as_ushort(h1) << 16) | __bfloat16_as_ushort(h0);
                *(uint32_t*)(sm + 32768 + off) =
                    ((uint32_t)__bfloat16_as_ushort(l1) << 16) | __bfloat16_as_ushort(l0);
            }
        }
    __syncthreads();                               // H1 tile ready in A

    const int t = (int)(row0 >> 14), b = (int)((row0 >> 12) & 3);
    float* gfrow = g_gf + (t * 4 + b) * 1024;
    const float inv = 1.f / 4096.f;

    for (int nb = 0; nb < 8; nb++) {
        CP_WAIT1(); __syncthreads();
        ACC_ZERO(acc);
        mma_core(sA, (nb & 1) ? sB1 : sB0, wm, wn, lane, acc);
        __syncthreads();
        if (nb + 2 < 8) {
            uint32_t dst = (nb & 1) ? sB1 : sB0;
            fill_async(dst, g_w2h + (nb + 2) * 16384, tid);
            fill_async(dst + 32768, g_w2l + (nb + 2) * 16384, tid);
        }
        CP_COMMIT();
        // fused leaky + column-sum epilogue (register + shuffle)
#pragma unroll
        for (int ni = 0; ni < 4; ni++) {
            int c = wn * 32 + ni * 8 + (lane & 3) * 2;
            float2 bv = *(const float2*)(b2 + nb * 128 + c);
            float s0 = 0.f, s1 = 0.f;
#pragma unroll
            for (int mi = 0; mi < 4; mi++) {
                s0 += leaky_f(acc[mi][ni][0] + bv.x) + leaky_f(acc[mi][ni][2] + bv.x);
                s1 += leaky_f(acc[mi][ni][1] + bv.y) + leaky_f(acc[mi][ni][3] + bv.y);
            }
#pragma unroll
            for (int o = 4; o <= 16; o <<= 1) {
                s0 += __shfl_xor_sync(0xffffffffu, s0, o);
                s1 += __shfl_xor_sync(0xffffffffu, s1, o);
            }
            if (lane < 4) {
                atomicAdd(&gfrow[nb * 128 + c], s0 * inv);
                atomicAdd(&gfrow[nb * 128 + c + 1], s1 * inv);
            }
        }
    }
}

// ---------------- XLR: A resident, 4 B tiles streamed, register store ----------------
#define XLSM 196608
__global__ __launch_bounds__(256, 1) void xlr_kernel() {
    extern __shared__ char sm[];
    const uint32_t sA = s2u(sm), sB0 = sA + 65536, sB1 = sA + 131072;
    const int tid = threadIdx.x, lane = tid & 31, wid = tid >> 5;
    const int wm = wid & 1, wn = wid >> 1;
    const int z = blockIdx.y;
    const size_t row0 = (size_t)blockIdx.x * 128;
    const __nv_bfloat16* Wh = (z == 4) ? g_wlh : g_wrh;
    const __nv_bfloat16* Wl = (z == 4) ? g_wll : g_wrl;

    fill_async(sA, g_sh + ((size_t)z * NPTS + row0) * 128, tid);
    fill_async(sA + 32768, g_sl + ((size_t)z * NPTS + row0) * 128, tid);
    fill_async(sB0, Wh, tid); fill_async(sB0 + 32768, Wl, tid); CP_COMMIT();
    fill_async(sB1, Wh + 16384, tid); fill_async(sB1 + 32768, Wl + 16384, tid); CP_COMMIT();

    float* dstb = g_XLR + ((size_t)z * NPTS + row0) * 512;
    for (int nb = 0; nb < 4; nb++) {
        CP_WAIT1(); __syncthreads();
        float acc[4][4][4];
        ACC_ZERO(acc);
        mma_core(sA, (nb & 1) ? sB1 : sB0, wm, wn, lane, acc);
        __syncthreads();
        if (nb + 2 < 4) {
            uint32_t dst = (nb & 1) ? sB1 : sB0;
            fill_async(dst, Wh + (nb + 2) * 16384, tid);
            fill_async(dst + 32768, Wl + (nb + 2) * 16384, tid);
        }
        CP_COMMIT();
#pragma unroll
        for (int mi = 0; mi < 4; mi++)
#pragma unroll
            for (int ni = 0; ni < 4; ni++) {
                int r = wm * 64 + mi * 16 + (lane >> 2);
                int c = wn * 32 + ni * 8 + (lane & 3) * 2;
                *(float2*)(dstb + (size_t)r * 512 + nb * 128 + c) =
                    make_float2(acc[mi][ni][0], acc[mi][ni][1]);
                *(float2*)(dstb + (size_t)(r + 8) * 512 + nb * 128 + c) =
                    make_float2(acc[mi][ni][2], acc[mi][ni][3]);
            }
    }
}

// ---------------- KNN: A resident, candidates streamed, stage into dead B buffer ----------------
// A@0 64K, B0@65536, B1@131072, xn@196608 (2x512B), td@197632, ti@206336 -> 215040
#define KNSM 215040
__global__ __launch_bounds__(256, 1) void knn_kernel() {
    extern __shared__ char sm[];
    const uint32_t sA = s2u(sm);
    const int tid = threadIdx.x, lane = tid & 31, wid = tid >> 5;
    const int wm = wid & 1, wn = wid >> 1;
    const int qt = blockIdx.x, b = blockIdx.y, fr = blockIdx.z;
    float* td = (float*)(sm + 197632) + (tid & 127) * 17;
    int*   ti = (int*)(sm + 206336)   + (tid & 127) * 17;

    const size_t yoff = ((size_t)4 * NPTS + b * MP + qt * 128) * 128;
    const size_t xbase = ((size_t)fr * NPTS + b * MP) * 128;
    const float* xng = g_xn + fr * NPTS + b * MP;

    fill_async(sA, g_sh + yoff, tid);
    fill_async(sA + 32768, g_sl + yoff, tid);
    fill_async(sA + 65536, g_sh + xbase, tid);            // chunk 0 -> B0
    fill_async(sA + 65536 + 32768, g_sl + xbase, tid);
    if (tid < 32) CP16(sA + 196608 + tid * 16, xng + tid * 4);
    CP_COMMIT();
    if (tid < 128) {
#pragma unroll
        for (int j = 0; j < 16; j++) { td[j] = 3.0e38f; ti[j] = 0; }
    }
    float worst = 3.0e38f;
    CP_WAIT0(); __syncthreads();

    for (int cc = 0; cc < 32; cc++) {
        const int cur = cc & 1, nxt = cur ^ 1;
        const uint32_t sBc = sA + 65536 + cur * 65536;
        if (cc + 1 < 32) {                                // prefetch next chunk (overlaps all below)
            const uint32_t sBn = sA + 65536 + nxt * 65536;
            fill_async(sBn, g_sh + xbase + (size_t)(cc + 1) * 128 * 128, tid);
            fill_async(sBn + 32768, g_sl + xbase + (size_t)(cc + 1) * 128 * 128, tid);
            if (tid < 32) CP16(sA + 196608 + nxt * 512 + tid * 16, xng + (cc + 1) * 128 + tid * 4);
        }
        CP_COMMIT();

        float acc[4][4][4];
        ACC_ZERO(acc);
        mma_core(sA, sBc, wm, wn, lane, acc);
        __syncthreads();                                  // B[cur] reads done
        float* stg = (float*)(sm + 65536 + cur * 65536);  // stage into dead B[cur]
#pragma unroll
        for (int mi = 0; mi < 4; mi++)
#pragma unroll
            for (int ni = 0; ni < 4; ni++) {
                int r = wm * 64 + mi * 16 + (lane >> 2);
                int c = wn * 32 + ni * 8 + (lane & 3) * 2;
                *(float2*)&stg[r * 128 + c] = make_float2(acc[mi][ni][0], acc[mi][ni][1]);
                *(float2*)&stg[(r + 8) * 128 + c] = make_float2(acc[mi][ni][2], acc[mi][ni][3]);
            }
        __syncthreads();
        if (tid < 128) {                                  // staggered scan, conflict-free
            const int q = tid;
            const float* xv = (const float*)(sm + 196608 + cur * 512);
            for (int c0 = 0; c0 < 128; c0++) {
                int c = (c0 + q) & 127;
                float s = xv[c] - 2.f * stg[q * 128 + c];
                if (s < worst) {
                    int cand = cc * 128 + c, p = 15;
                    while (p > 0 && td[p - 1] > s) { td[p] = td[p - 1]; ti[p] = ti[p - 1]; p--; }
                    td[p] = s; ti[p] = cand;
                    worst = td[15];
                }
            }
        }
        CP_WAIT0(); __syncthreads();
    }
    if (tid < 128) {
        const size_t nrow = ((size_t)fr * NPTS + b * MP + qt * 128 + tid) * KNB;
#pragma unroll
        for (int j = 0; j < 16; j++) g_nbr[nrow + j] = b * MP + ti[j];
    }
}

// ---------------- attn / gat / final (validated) ----------------
__global__ void attn_kernel() {
    __shared__ float sc[16];
    const int tid = threadIdx.x, w = tid >> 5, lane = tid & 31;
    const int b = w >> 2, t = w & 3;
    float acc = 0.f;
    for (int g = lane; g < 1024; g += 32)
        acc += g_gf[(16 + b) * 1024 + g] * g_gf[(t * 4 + b) * 1024 + g];
#pragma unroll
    for (int o = 16; o; o >>= 1) acc += __shfl_xor_sync(0xffffffffu, acc, o);
    if (lane == 0) sc[b * 4 + t] = acc * (1.f / 32.f);
    __syncthreads();
    if (tid < 4) {
        int bb = tid;
        float m = sc[bb * 4];
        for (int i = 1; i < 4; i++) m = fmaxf(m, sc[bb * 4 + i]);
        float e[4], s = 0.f;
        for (int i = 0; i < 4; i++) { e[i] = expf(sc[bb * 4 + i] - m); s += e[i]; }
        for (int i = 0; i < 4; i++) g_attn[bb * 4 + i] = e[i] / s;
    }
}
__global__ __launch_bounds__(128) void gat_kernel(const float* __restrict__ att_w) {
    __shared__ float xls[16 * 512], xrs[512], aws[512], es[64], as_[64];
    __shared__ int nb[16];
    const int tid = threadIdx.x, n = blockIdx.x, fr = blockIdx.y;
    const float* XL = g_XLR + (size_t)4 * NPTS * 512;
    const float* XR = g_XLR + (size_t)fr * NPTS * 512;
    *(float4*)&xrs[tid * 4] = *(const float4*)(XR + (size_t)n * 512 + tid * 4);
    *(float4*)&aws[tid * 4] = *(const float4*)(att_w + tid * 4);
    if (tid < 16) nb[tid] = g_nbr[((size_t)fr * NPTS + n) * KNB + tid];
    __syncthreads();
#pragma unroll
    for (int k = 0; k < 16; k++)
        *(float4*)&xls[k * 512 + tid * 4] = *(const float4*)(XL + (size_t)nb[k] * 512 + tid * 4);
    __syncthreads();
    if (tid < 64) {
        const int k = tid & 15, h = tid >> 4;
        float acc = 0.f;
#pragma unroll 4
        for (int cc = 0; cc < 128; cc++) {
            int c = (tid + cc) & 127;
            float v = xls[k * 512 + h * 128 + c] + xrs[h * 128 + c];
            acc += aws[h * 128 + c] * (v < 0.f ? 0.2f * v : v);
        }
        es[h * 16 + k] = acc;
    }
    __syncthreads();
    if (tid < 4) {
        const int h = tid;
        float m = -1e30f;
        for (int k = 0; k < 16; k++) m = fmaxf(m, es[h * 16 + k]);
        float ex[16], s = 0.f;
        for (int k = 0; k < 16; k++) { ex[k] = expf(es[h * 16 + k] - m); s += ex[k]; }
        for (int k = 0; k < 16; k++) as_[h * 16 + k] = ex[k] / s;
    }
    __syncthreads();
    float o = 0.f;
#pragma unroll
    for (int h = 0; h < 4; h++) {
        float oh = 0.f;
#pragma unroll
        for (int k = 0; k < 16; k++) oh += as_[h * 16 + k] * xls[k * 512 + h * 128 + tid];
        o += oh;
    }
    g_res[((size_t)fr * NPTS + n) * 128 + tid] = o * 0.25f;
}
__global__ __launch_bounds__(128) void final_kernel(const float* __restrict__ seq, float* __restrict__ out) {
    const int n = blockIdx.x, c = threadIdx.x, b = n >> 12;
    float w = 0.f;
#pragma unroll
    for (int i = 0; i < 4; i++)
        w += g_attn[b * 4 + i] * g_res[((size_t)i * NPTS + n) * 128 + c];
    const float* last = seq + (size_t)4 * NPTS * 128;
    out[(size_t)n * 256 + c] = last[(size_t)n * 128 + c];
    out[(size_t)n * 256 + 128 + c] = w;
}

// ---------------- launch ----------------
extern "C" void kernel_launch(void* const* d_in, const int* in_sizes, int n_in,
                              void* d_out, int out_size) {
    (void)in_sizes; (void)n_in; (void)out_size;
    const float* seq = (const float*)d_in[0];
    const float* W1  = (const float*)d_in[1];
    const float* b1  = (const float*)d_in[2];
    const float* W2  = (const float*)d_in[3];
    const float* b2  = (const float*)d_in[4];
    const float* Wl  = (const float*)d_in[5];
    const float* Wr  = (const float*)d_in[6];
    const float* aw  = (const float*)d_in[7];
    float* out = (float*)d_out;

    __nv_bfloat16 *pw1h, *pw1l, *pw2h, *pw2l, *pwlh, *pwll, *pwrh, *pwrl;
    cudaGetSymbolAddress((void**)&pw1h, g_w1h); cudaGetSymbolAddress((void**)&pw1l, g_w1l);
    cudaGetSymbolAddress((void**)&pw2h, g_w2h); cudaGetSymbolAddress((void**)&pw2l, g_w2l);
    cudaGetSymbolAddress((void**)&pwlh, g_wlh); cudaGetSymbolAddress((void**)&pwll, g_wll);
    cudaGetSymbolAddress((void**)&pwrh, g_wrh); cudaGetSymbolAddress((void**)&pwrl, g_wrl);

    cudaFuncSetAttribute(gf_kernel,  cudaFuncAttributeMaxDynamicSharedMemorySize, GFSM);
    cudaFuncSetAttribute(xlr_kernel, cudaFuncAttributeMaxDynamicSharedMemorySize, XLSM);
    cudaFuncSetAttribute(knn_kernel, cudaFuncAttributeMaxDynamicSharedMemorySize, KNSM);

    zero_gf_kernel<<<80, 256>>>();
    split_seq_kernel<<<10240, 256>>>(seq);
    norm_kernel<<<512, 128>>>(seq);
    tsplit_kernel<<<dim3(4, 4),  dim3(32, 8)>>>(W1, pw1h, pw1l, 128);
    tsplit_kernel<<<dim3(32, 4), dim3(32, 8)>>>(W2, pw2h, pw2l, 1024);
    tsplit_kernel<<<dim3(16, 4), dim3(32, 8)>>>(Wl, pwlh, pwll, 512);
    tsplit_kernel<<<dim3(16, 4), dim3(32, 8)>>>(Wr, pwrh, pwrl, 512);

    gf_kernel<<<640, 256, GFSM>>>(b1, b2);
    attn_kernel<<<1, 512>>>();
    xlr_kernel<<<dim3(128, 5), 256, XLSM>>>();
    knn_kernel<<<dim3(32, 4, 4), 256, KNSM>>>();
    gat_kernel<<<dim3(NPTS, 4), 128>>>(aw);
    final_kernel<<<NPTS, 128>>>(seq, out);
}

// round 7
// speedup vs baseline: 1.4821x; 1.4821x over previous
#include <cuda_runtime.h>
#include <cuda_bf16.h>
#include <cstdint>

#define NPTS 16384
#define MP   4096
#define KNB  16

// ---------------- helpers ----------------
__device__ __forceinline__ uint32_t s2u(const void* p) {
    uint32_t a;
    asm("{ .reg .u64 t; cvta.to.shared.u64 t, %1; cvt.u32.u64 %0, t; }" : "=r"(a) : "l"(p));
    return a;
}
#define CP16(dst, src) asm volatile("cp.async.cg.shared.global [%0], [%1], 16;" :: "r"(dst), "l"(src))
#define CP_COMMIT()    asm volatile("cp.async.commit_group;" ::: "memory")
#define CP_WAIT0()     asm volatile("cp.async.wait_group 0;" ::: "memory")
#define CP_WAIT1()     asm volatile("cp.async.wait_group 1;" ::: "memory")

// [128][128] bf16 tile, 256B rows, 16B chunks XOR-swizzled by row
__device__ __forceinline__ uint32_t tile_off(int r, int c16) {
    return (uint32_t)(r * 256 + ((c16 ^ (r & 7)) << 4));
}
template <int NT>
__device__ __forceinline__ void fill_tile_async(uint32_t dst, const __nv_bfloat16* __restrict__ src, int tid) {
#pragma unroll
    for (int it = 0; it < 2048 / NT; it++) {
        int idx = tid + it * NT;
        int r = idx >> 4, c16 = idx & 15;
        CP16(dst + tile_off(r, c16), src + r * 128 + c16 * 8);
    }
}
__device__ __forceinline__ void ldmA(uint32_t* a, uint32_t base, int mrow, int kcol, int lane) {
    uint32_t addr = base + tile_off(mrow + (lane & 15), (kcol >> 3) + (lane >> 4));
    asm volatile("ldmatrix.sync.aligned.m8n8.x4.shared.b16 {%0,%1,%2,%3}, [%4];"
        : "=r"(a[0]), "=r"(a[1]), "=r"(a[2]), "=r"(a[3]) : "r"(addr));
}
__device__ __forceinline__ void ldmB(uint32_t* b, uint32_t base, int ncol, int kcol, int lane) {
    uint32_t addr = base + tile_off(ncol + (lane & 7), (kcol >> 3) + ((lane >> 3) & 1));
    asm volatile("ldmatrix.sync.aligned.m8n8.x2.shared.b16 {%0,%1}, [%2];"
        : "=r"(b[0]), "=r"(b[1]) : "r"(addr));
}
__device__ __forceinline__ void mma16816(float* d, const uint32_t* a, const uint32_t* b) {
    asm volatile("mma.sync.aligned.m16n8k16.row.col.f32.bf16.bf16.f32 "
        "{%0,%1,%2,%3}, {%4,%5,%6,%7}, {%8,%9}, {%0,%1,%2,%3};"
        : "+f"(d[0]), "+f"(d[1]), "+f"(d[2]), "+f"(d[3])
        : "r"(a[0]), "r"(a[1]), "r"(a[2]), "r"(a[3]), "r"(b[0]), "r"(b[1]));
}
__device__ __forceinline__ float leaky_f(float v) { return v < 0.f ? 0.2f * v : v; }

// split-bf16 3-product 128x128x128 tile for 8 warps: warp (wm,wn) owns 64x32
__device__ __forceinline__ void mma_core(uint32_t sA, uint32_t sB, int wm, int wn, int lane,
                                         float acc[4][4][4]) {
#pragma unroll 1
    for (int ks = 0; ks < 8; ks++) {
        const int kc = ks * 16;
        uint32_t ah[4][4], al[4][4], bh[4][2], bl[4][2];
#pragma unroll
        for (int mi = 0; mi < 4; mi++) {
            ldmA(ah[mi], sA, wm * 64 + mi * 16, kc, lane);
            ldmA(al[mi], sA + 32768, wm * 64 + mi * 16, kc, lane);
        }
#pragma unroll
        for (int ni = 0; ni < 4; ni++) {
            ldmB(bh[ni], sB, wn * 32 + ni * 8, kc, lane);
            ldmB(bl[ni], sB + 32768, wn * 32 + ni * 8, kc, lane);
        }
#pragma unroll
        for (int mi = 0; mi < 4; mi++)
#pragma unroll
            for (int ni = 0; ni < 4; ni++) {
                mma16816(acc[mi][ni], ah[mi], bh[ni]);
                mma16816(acc[mi][ni], ah[mi], bl[ni]);
                mma16816(acc[mi][ni], al[mi], bh[ni]);
            }
    }
}
#define ACC_ZERO4(acc) do { \
    _Pragma("unroll") for (int mi = 0; mi < 4; mi++) \
    _Pragma("unroll") for (int ni = 0; ni < 4; ni++) \
    _Pragma("unroll") for (int j = 0; j < 4; j++) acc[mi][ni][j] = 0.f; } while (0)

// ---------------- scratch ----------------
__device__ __nv_bfloat16 g_sh[81920 * 128], g_sl[81920 * 128];
__device__ __nv_bfloat16 g_w1h[128 * 128],  g_w1l[128 * 128];
__device__ __nv_bfloat16 g_w2h[1024 * 128], g_w2l[1024 * 128];
__device__ __nv_bfloat16 g_wlh[512 * 128],  g_wll[512 * 128];
__device__ __nv_bfloat16 g_wrh[512 * 128],  g_wrl[512 * 128];
__device__ float g_xn[65536];
__device__ float g_XLR[5 * 16384 * 512];
__device__ float g_gf[5 * 4 * 1024];
__device__ float g_attn[16];
__device__ int   g_nbr[4 * 16384 * 16];
__device__ float g_res[4 * 16384 * 128];

// ---------------- preludes ----------------
__global__ void zero_gf_kernel() {
    int i = blockIdx.x * 256 + threadIdx.x;
    if (i < 5 * 4 * 1024) g_gf[i] = 0.f;
}
__global__ void split_seq_kernel(const float* __restrict__ seq) {
    size_t i = (size_t)blockIdx.x * 256 + threadIdx.x;
    float4 v = ((const float4*)seq)[i];
    float x[4] = {v.x, v.y, v.z, v.w};
    unsigned short h[4], l[4];
#pragma unroll
    for (int j = 0; j < 4; j++) {
        __nv_bfloat16 hb = __float2bfloat16(x[j]);
        h[j] = __bfloat16_as_ushort(hb);
        l[j] = __bfloat16_as_ushort(__float2bfloat16(x[j] - __bfloat162float(hb)));
    }
    uint2 H, L;
    H.x = ((uint32_t)h[1] << 16) | h[0]; H.y = ((uint32_t)h[3] << 16) | h[2];
    L.x = ((uint32_t)l[1] << 16) | l[0]; L.y = ((uint32_t)l[3] << 16) | l[2];
    ((uint2*)g_sh)[i] = H; ((uint2*)g_sl)[i] = L;
}
__global__ void norm_kernel(const float* __restrict__ seq) {
    int r = blockIdx.x * 128 + threadIdx.x;
    const float4* p = (const float4*)(seq + (size_t)r * 128);
    float s = 0.f;
#pragma unroll 8
    for (int i = 0; i < 32; i++) { float4 v = p[i]; s += v.x*v.x + v.y*v.y + v.z*v.z + v.w*v.w; }
    g_xn[r] = s;
}
__global__ void tsplit_kernel(const float* __restrict__ src, __nv_bfloat16* __restrict__ dh,
                              __nv_bfloat16* __restrict__ dl, int N) {
    __shared__ float t[32][33];
    int n0 = blockIdx.x * 32, k0 = blockIdx.y * 32;
    int tx = threadIdx.x, ty = threadIdx.y;
#pragma unroll
    for (int j = 0; j < 4; j++) t[ty + 8 * j][tx] = src[(size_t)(k0 + ty + 8 * j) * N + n0 + tx];
    __syncthreads();
#pragma unroll
    for (int j = 0; j < 4; j++) {
        int n = n0 + ty + 8 * j, k = k0 + tx;
        float v = t[tx][ty + 8 * j];
        __nv_bfloat16 hb = __float2bfloat16(v);
        dh[(size_t)n * 128 + k] = hb;
        dl[(size_t)n * 128 + k] = __float2bfloat16(v - __bfloat162float(hb));
    }
}

// ---------------- KNN: 512 threads, 16 warps, register top-16 with pair merge ----------------
// A@0 (64K), B0@65536 (64K), B1@131072 (64K), xn@196608 (2x512B). Merge scratch overlays A at end.
#define KNSM 197632
__device__ __forceinline__ int stgoff(int q, int c) {   // XOR-swizzled f32 staging [128][128]
    return q * 128 + ((((c >> 2) ^ (q & 7)) << 2) | (c & 3));
}
__global__ __launch_bounds__(512, 1) void knn_kernel() {
    extern __shared__ char sm[];
    const uint32_t sA = s2u(sm);
    const int tid = threadIdx.x, lane = tid & 31, wid = tid >> 5;
    const int wm = wid & 3, wn = wid >> 2;               // 32x32 warp tile
    const int qt = blockIdx.x, b = blockIdx.y, fr = blockIdx.z;

    const size_t yoff = ((size_t)4 * NPTS + b * MP + qt * 128) * 128;
    const size_t xbase = ((size_t)fr * NPTS + b * MP) * 128;
    const float* xng = g_xn + fr * NPTS + b * MP;

    fill_tile_async<512>(sA, g_sh + yoff, tid);
    fill_tile_async<512>(sA + 32768, g_sl + yoff, tid);
    fill_tile_async<512>(sA + 65536, g_sh + xbase, tid);
    fill_tile_async<512>(sA + 65536 + 32768, g_sl + xbase, tid);
    if (tid < 32) CP16(sA + 196608 + tid * 16, xng + tid * 4);
    CP_COMMIT();

    float rd[16]; int ri[16];
#pragma unroll
    for (int j = 0; j < 16; j++) { rd[j] = 3.0e38f; ri[j] = 0; }
    CP_WAIT0(); __syncthreads();

    for (int cc = 0; cc < 32; cc++) {
        const int cur = cc & 1, nxt = cur ^ 1;
        const uint32_t sBc = sA + 65536 + cur * 65536;
        if (cc + 1 < 32) {
            const uint32_t sBn = sA + 65536 + nxt * 65536;
            fill_tile_async<512>(sBn, g_sh + xbase + (size_t)(cc + 1) * 16384, tid);
            fill_tile_async<512>(sBn + 32768, g_sl + xbase + (size_t)(cc + 1) * 16384, tid);
            if (tid < 32) CP16(sA + 196608 + nxt * 512 + tid * 16, xng + (cc + 1) * 128 + tid * 4);
        }
        CP_COMMIT();

        float acc[2][4][4];
#pragma unroll
        for (int mi = 0; mi < 2; mi++)
#pragma unroll
            for (int ni = 0; ni < 4; ni++)
#pragma unroll
                for (int j = 0; j < 4; j++) acc[mi][ni][j] = 0.f;
#pragma unroll 1
        for (int ks = 0; ks < 8; ks++) {
            const int kc = ks * 16;
            uint32_t ah[2][4], al[2][4], bh[4][2], bl[4][2];
#pragma unroll
            for (int mi = 0; mi < 2; mi++) {
                ldmA(ah[mi], sA, wm * 32 + mi * 16, kc, lane);
                ldmA(al[mi], sA + 32768, wm * 32 + mi * 16, kc, lane);
            }
#pragma unroll
            for (int ni = 0; ni < 4; ni++) {
                ldmB(bh[ni], sBc, wn * 32 + ni * 8, kc, lane);
                ldmB(bl[ni], sBc + 32768, wn * 32 + ni * 8, kc, lane);
            }
#pragma unroll
            for (int mi = 0; mi < 2; mi++)
#pragma unroll
                for (int ni = 0; ni < 4; ni++) {
                    mma16816(acc[mi][ni], ah[mi], bh[ni]);
                    mma16816(acc[mi][ni], ah[mi], bl[ni]);
                    mma16816(acc[mi][ni], al[mi], bh[ni]);
                }
        }
        __syncthreads();                                  // B[cur] reads done
        float* stg = (float*)(sm + 65536 + cur * 65536);  // dead B[cur]
#pragma unroll
        for (int mi = 0; mi < 2; mi++)
#pragma unroll
            for (int ni = 0; ni < 4; ni++) {
                int r = wm * 32 + mi * 16 + (lane >> 2);
                int c = wn * 32 + ni * 8 + (lane & 3) * 2;
                *(float2*)&stg[stgoff(r, c)] = make_float2(acc[mi][ni][0], acc[mi][ni][1]);
                *(float2*)&stg[stgoff(r + 8, c)] = make_float2(acc[mi][ni][2], acc[mi][ni][3]);
            }
        __syncthreads();
        if (tid < 256) {                                  // 2 threads per query
            const int q = tid >> 1, hf = tid & 1;
            const float* xv = (const float*)(sm + 196608 + cur * 512);
#pragma unroll 4
            for (int c0 = 0; c0 < 64; c0++) {
                int c = hf * 64 + ((c0 + q + hf * 16) & 63);
                float s = xv[c] - 2.f * stg[stgoff(q, c)];
                if (s < rd[15]) {
                    rd[15] = s; ri[15] = cc * 128 + c;
#pragma unroll
                    for (int j = 15; j > 0; j--) {
                        if (rd[j] < rd[j - 1]) {
                            float tf = rd[j]; rd[j] = rd[j - 1]; rd[j - 1] = tf;
                            int tx = ri[j]; ri[j] = ri[j - 1]; ri[j - 1] = tx;
                        }
                    }
                }
            }
        }
        CP_WAIT0(); __syncthreads();
    }

    // merge pairs (A area is dead now)
    float* md = (float*)sm;            // [256][16]
    int*   mi_ = (int*)(sm + 16384);   // [256][16]
    if (tid < 256) {
#pragma unroll
        for (int j = 0; j < 16; j++) { md[tid * 16 + j] = rd[j]; mi_[tid * 16 + j] = ri[j]; }
    }
    __syncthreads();
    if (tid < 128) {
        const float* da = &md[(2 * tid) * 16];
        const float* db = &md[(2 * tid + 1) * 16];
        const int* ia = &mi_[(2 * tid) * 16];
        const int* ib = &mi_[(2 * tid + 1) * 16];
        int pa = 0, pb = 0;
        const size_t nrow = ((size_t)fr * NPTS + b * MP + qt * 128 + tid) * KNB;
#pragma unroll
        for (int j = 0; j < 16; j++) {
            float va = da[pa], vb = db[pb];
            bool ta = (va < vb) || (va == vb && ia[pa] < ib[pb]);
            g_nbr[nrow + j] = b * MP + (ta ? ia[pa] : ib[pb]);
            if (ta) pa++; else pb++;
        }
    }
}

// ---------------- fused H1 + gf: A resident, W2 streamed double-buffered ----------------
#define GFSM 196608
__global__ __launch_bounds__(256, 1) void gf_kernel(const float* __restrict__ b1,
                                                    const float* __restrict__ b2) {
    extern __shared__ char sm[];
    const uint32_t sA = s2u(sm), sB0 = sA + 65536, sB1 = sA + 131072;
    const int tid = threadIdx.x, lane = tid & 31, wid = tid >> 5;
    const int wm = wid & 1, wn = wid >> 1;
    const size_t row0 = (size_t)blockIdx.x * 128;

    fill_tile_async<256>(sA, g_sh + row0 * 128, tid);
    fill_tile_async<256>(sA + 32768, g_sl + row0 * 128, tid);
    fill_tile_async<256>(sB0, g_w1h, tid);
    fill_tile_async<256>(sB0 + 32768, g_w1l, tid);
    CP_COMMIT(); CP_WAIT0(); __syncthreads();

    float acc[4][4][4];
    ACC_ZERO4(acc);
    mma_core(sA, sB0, wm, wn, lane, acc);
    __syncthreads();

    fill_tile_async<256>(sB0, g_w2h, tid); fill_tile_async<256>(sB0 + 32768, g_w2l, tid); CP_COMMIT();
    fill_tile_async<256>(sB1, g_w2h + 16384, tid); fill_tile_async<256>(sB1 + 32768, g_w2l + 16384, tid); CP_COMMIT();

#pragma unroll
    for (int mi = 0; mi < 4; mi++)
#pragma unroll
        for (int ni = 0; ni < 4; ni++) {
            int r = wm * 64 + mi * 16 + (lane >> 2);
            int c = wn * 32 + ni * 8 + (lane & 3) * 2;
            float2 bv = *(const float2*)(b1 + c);
#pragma unroll
            for (int half = 0; half < 2; half++) {
                int rr = r + half * 8;
                float v0 = leaky_f(acc[mi][ni][half * 2]     + bv.x);
                float v1 = leaky_f(acc[mi][ni][half * 2 + 1] + bv.y);
                __nv_bfloat16 h0 = __float2bfloat16(v0), h1 = __float2bfloat16(v1);
                __nv_bfloat16 l0 = __float2bfloat16(v0 - __bfloat162float(h0));
                __nv_bfloat16 l1 = __float2bfloat16(v1 - __bfloat162float(h1));
                uint32_t off = tile_off(rr, c >> 3) + (c & 7) * 2;
                *(uint32_t*)(sm + off) =
                    ((uint32_t)__bfloat16_as_ushort(h1) << 16) | __bfloat16_as_ushort(h0);
                *(uint32_t*)(sm + 32768 + off) =
                    ((uint32_t)__bfloat16_as_ushort(l1) << 16) | __bfloat16_as_ushort(l0);
            }
        }
    __syncthreads();

    const int t = (int)(row0 >> 14), b = (int)((row0 >> 12) & 3);
    float* gfrow = g_gf + (t * 4 + b) * 1024;
    const float inv = 1.f / 4096.f;

    for (int nb = 0; nb < 8; nb++) {
        CP_WAIT1(); __syncthreads();
        ACC_ZERO4(acc);
        mma_core(sA, (nb & 1) ? sB1 : sB0, wm, wn, lane, acc);
        __syncthreads();
        if (nb + 2 < 8) {
            uint32_t dst = (nb & 1) ? sB1 : sB0;
            fill_tile_async<256>(dst, g_w2h + (nb + 2) * 16384, tid);
            fill_tile_async<256>(dst + 32768, g_w2l + (nb + 2) * 16384, tid);
        }
        CP_COMMIT();
#pragma unroll
        for (int ni = 0; ni < 4; ni++) {
            int c = wn * 32 + ni * 8 + (lane & 3) * 2;
            float2 bv = *(const float2*)(b2 + nb * 128 + c);
            float s0 = 0.f, s1 = 0.f;
#pragma unroll
            for (int mi = 0; mi < 4; mi++) {
                s0 += leaky_f(acc[mi][ni][0] + bv.x) + leaky_f(acc[mi][ni][2] + bv.x);
                s1 += leaky_f(acc[mi][ni][1] + bv.y) + leaky_f(acc[mi][ni][3] + bv.y);
            }
#pragma unroll
            for (int o = 4; o <= 16; o <<= 1) {
                s0 += __shfl_xor_sync(0xffffffffu, s0, o);
                s1 += __shfl_xor_sync(0xffffffffu, s1, o);
            }
            if (lane < 4) {
                atomicAdd(&gfrow[nb * 128 + c], s0 * inv);
                atomicAdd(&gfrow[nb * 128 + c + 1], s1 * inv);
            }
        }
    }
}

// ---------------- XLR ----------------
#define XLSM 196608
__global__ __launch_bounds__(256, 1) void xlr_kernel() {
    extern __shared__ char sm[];
    const uint32_t sA = s2u(sm), sB0 = sA + 65536, sB1 = sA + 131072;
    const int tid = threadIdx.x, lane = tid & 31, wid = tid >> 5;
    const int wm = wid & 1, wn = wid >> 1;
    const int z = blockIdx.y;
    const size_t row0 = (size_t)blockIdx.x * 128;
    const __nv_bfloat16* Wh = (z == 4) ? g_wlh : g_wrh;
    const __nv_bfloat16* Wl = (z == 4) ? g_wll : g_wrl;

    fill_tile_async<256>(sA, g_sh + ((size_t)z * NPTS + row0) * 128, tid);
    fill_tile_async<256>(sA + 32768, g_sl + ((size_t)z * NPTS + row0) * 128, tid);
    fill_tile_async<256>(sB0, Wh, tid); fill_tile_async<256>(sB0 + 32768, Wl, tid); CP_COMMIT();
    fill_tile_async<256>(sB1, Wh + 16384, tid); fill_tile_async<256>(sB1 + 32768, Wl + 16384, tid); CP_COMMIT();

    float* dstb = g_XLR + ((size_t)z * NPTS + row0) * 512;
    for (int nb = 0; nb < 4; nb++) {
        CP_WAIT1(); __syncthreads();
        float acc[4][4][4];
        ACC_ZERO4(acc);
        mma_core(sA, (nb & 1) ? sB1 : sB0, wm, wn, lane, acc);
        __syncthreads();
        if (nb + 2 < 4) {
            uint32_t dst = (nb & 1) ? sB1 : sB0;
            fill_tile_async<256>(dst, Wh + (nb + 2) * 16384, tid);
            fill_tile_async<256>(dst + 32768, Wl + (nb + 2) * 16384, tid);
        }
        CP_COMMIT();
#pragma unroll
        for (int mi = 0; mi < 4; mi++)
#pragma unroll
            for (int ni = 0; ni < 4; ni++) {
                int r = wm * 64 + mi * 16 + (lane >> 2);
                int c = wn * 32 + ni * 8 + (lane & 3) * 2;
                *(float2*)(dstb + (size_t)r * 512 + nb * 128 + c) =
                    make_float2(acc[mi][ni][0], acc[mi][ni][1]);
                *(float2*)(dstb + (size_t)(r + 8) * 512 + nb * 128 + c) =
                    make_float2(acc[mi][ni][2], acc[mi][ni][3]);
            }
    }
}

// ---------------- attn / gat / final ----------------
__global__ void attn_kernel() {
    __shared__ float sc[16];
    const int tid = threadIdx.x, w = tid >> 5, lane = tid & 31;
    const int b = w >> 2, t = w & 3;
    float acc = 0.f;
    for (int g = lane; g < 1024; g += 32)
        acc += g_gf[(16 + b) * 1024 + g] * g_gf[(t * 4 + b) * 1024 + g];
#pragma unroll
    for (int o = 16; o; o >>= 1) acc += __shfl_xor_sync(0xffffffffu, acc, o);
    if (lane == 0) sc[b * 4 + t] = acc * (1.f / 32.f);
    __syncthreads();
    if (tid < 4) {
        int bb = tid;
        float m = sc[bb * 4];
        for (int i = 1; i < 4; i++) m = fmaxf(m, sc[bb * 4 + i]);
        float e[4], s = 0.f;
        for (int i = 0; i < 4; i++) { e[i] = expf(sc[bb * 4 + i] - m); s += e[i]; }
        for (int i = 0; i < 4; i++) g_attn[bb * 4 + i] = e[i] / s;
    }
}
__global__ __launch_bounds__(128) void gat_kernel(const float* __restrict__ att_w) {
    __shared__ float xls[16 * 512], xrs[512], aws[512], es[64], as_[64];
    __shared__ int nb[16];
    const int tid = threadIdx.x, n = blockIdx.x, fr = blockIdx.y;
    const float* XL = g_XLR + (size_t)4 * NPTS * 512;
    const float* XR = g_XLR + (size_t)fr * NPTS * 512;
    *(float4*)&xrs[tid * 4] = *(const float4*)(XR + (size_t)n * 512 + tid * 4);
    *(float4*)&aws[tid * 4] = *(const float4*)(att_w + tid * 4);
    if (tid < 16) nb[tid] = g_nbr[((size_t)fr * NPTS + n) * KNB + tid];
    __syncthreads();
#pragma unroll
    for (int k = 0; k < 16; k++)
        *(float4*)&xls[k * 512 + tid * 4] = *(const float4*)(XL + (size_t)nb[k] * 512 + tid * 4);
    __syncthreads();
    {   // e[k][h]: 2 threads per (k,h), 64 cols each
        const int pr = tid >> 1, hf = tid & 1;
        const int k = pr & 15, h = pr >> 4;
        float acc = 0.f;
#pragma unroll 4
        for (int c0 = 0; c0 < 64; c0++) {
            int c = hf * 64 + ((c0 + pr + hf * 16) & 63);
            float v = xls[k * 512 + h * 128 + c] + xrs[h * 128 + c];
            acc += aws[h * 128 + c] * (v < 0.f ? 0.2f * v : v);
        }
        acc += __shfl_xor_sync(0xffffffffu, acc, 1);
        if (!hf) es[h * 16 + k] = acc;
    }
    __syncthreads();
    if (tid < 4) {
        const int h = tid;
        float m = -1e30f;
        for (int k = 0; k < 16; k++) m = fmaxf(m, es[h * 16 + k]);
        float ex[16], s = 0.f;
        for (int k = 0; k < 16; k++) { ex[k] = expf(es[h * 16 + k] - m); s += ex[k]; }
        for (int k = 0; k < 16; k++) as_[h * 16 + k] = ex[k] / s;
    }
    __syncthreads();
    float o = 0.f;
#pragma unroll
    for (int h = 0; h < 4; h++) {
        float oh = 0.f;
#pragma unroll
        for (int k = 0; k < 16; k++) oh += as_[h * 16 + k] * xls[k * 512 + h * 128 + tid];
        o += oh;
    }
    g_res[((size_t)fr * NPTS + n) * 128 + tid] = o * 0.25f;
}
__global__ __launch_bounds__(128) void final_kernel(const float* __restrict__ seq, float* __restrict__ out) {
    const int n = blockIdx.x, c = threadIdx.x, b = n >> 12;
    float w = 0.f;
#pragma unroll
    for (int i = 0; i < 4; i++)
        w += g_attn[b * 4 + i] * g_res[((size_t)i * NPTS + n) * 128 + c];
    const float* last = seq + (size_t)4 * NPTS * 128;
    out[(size_t)n * 256 + c] = last[(size_t)n * 128 + c];
    out[(size_t)n * 256 + 128 + c] = w;
}

// ---------------- launch (order chosen so ncu -s 5 -c 1 profiles knn_kernel) ----------------
extern "C" void kernel_launch(void* const* d_in, const int* in_sizes, int n_in,
                              void* d_out, int out_size) {
    (void)in_sizes; (void)n_in; (void)out_size;
    const float* seq = (const float*)d_in[0];
    const float* W1  = (const float*)d_in[1];
    const float* b1  = (const float*)d_in[2];
    const float* W2  = (const float*)d_in[3];
    const float* b2  = (const float*)d_in[4];
    const float* Wl  = (const float*)d_in[5];
    const float* Wr  = (const float*)d_in[6];
    const float* aw  = (const float*)d_in[7];
    float* out = (float*)d_out;

    __nv_bfloat16 *pw1h, *pw1l, *pw2h, *pw2l, *pwlh, *pwll, *pwrh, *pwrl;
    cudaGetSymbolAddress((void**)&pw1h, g_w1h); cudaGetSymbolAddress((void**)&pw1l, g_w1l);
    cudaGetSymbolAddress((void**)&pw2h, g_w2h); cudaGetSymbolAddress((void**)&pw2l, g_w2l);
    cudaGetSymbolAddress((void**)&pwlh, g_wlh); cudaGetSymbolAddress((void**)&pwll, g_wll);
    cudaGetSymbolAddress((void**)&pwrh, g_wrh); cudaGetSymbolAddress((void**)&pwrl, g_wrl);

    cudaFuncSetAttribute(gf_kernel,  cudaFuncAttributeMaxDynamicSharedMemorySize, GFSM);
    cudaFuncSetAttribute(xlr_kernel, cudaFuncAttributeMaxDynamicSharedMemorySize, XLSM);
    cudaFuncSetAttribute(knn_kernel, cudaFuncAttributeMaxDynamicSharedMemorySize, KNSM);

    zero_gf_kernel<<<80, 256>>>();                               // 1
    split_seq_kernel<<<10240, 256>>>(seq);                       // 2
    norm_kernel<<<512, 128>>>(seq);                              // 3
    tsplit_kernel<<<dim3(4, 4),  dim3(32, 8)>>>(W1, pw1h, pw1l, 128);   // 4
    tsplit_kernel<<<dim3(32, 4), dim3(32, 8)>>>(W2, pw2h, pw2l, 1024);  // 5
    knn_kernel<<<dim3(32, 4, 4), 512, KNSM>>>();                 // 6 <- ncu profiles this
    tsplit_kernel<<<dim3(16, 4), dim3(32, 8)>>>(Wl, pwlh, pwll, 512);
    tsplit_kernel<<<dim3(16, 4), dim3(32, 8)>>>(Wr, pwrh, pwrl, 512);
    gf_kernel<<<640, 256, GFSM>>>(b1, b2);
    attn_kernel<<<1, 512>>>();
    xlr_kernel<<<dim3(128, 5), 256, XLSM>>>();
    gat_kernel<<<dim3(NPTS, 4), 128>>>(aw);
    final_kernel<<<NPTS, 128>>>(seq, out);
}